// round 3
// baseline (speedup 1.0000x reference)
#include <cuda_runtime.h>
#include <cuda_bf16.h>
#include <cstdint>

// ============================================================================
// Problem constants
// ============================================================================
#define BATCH   4096
#define DIM     256
#define NROWS   8192          // 2*BATCH
#define INV_TAU 2.0f          // 1/0.5

// GEMM tiling: 128x128 output tile, K=256 fully resident
#define MT      128
#define NT      128
#define N_ITILE 64
#define N_JTILE 64
#define LDA     264           // padded row length in bf16 (+16B) -> conflict-free LDS

// ============================================================================
// Device-global scratch (no dynamic allocation allowed)
// ============================================================================
__device__ __align__(16) __nv_bfloat16 g_zn[NROWS * DIM];  // normalized, bf16
__device__ float g_rowsum[NROWS];

// ============================================================================
// Helpers
// ============================================================================
__device__ __forceinline__ uint32_t smem_to_u32(const void* smem_ptr) {
    uint32_t addr;
    asm("{ .reg .u64 tmp; cvta.to.shared.u64 tmp, %1; cvt.u32.u64 %0, tmp; }"
        : "=r"(addr) : "l"(smem_ptr));
    return addr;
}

__device__ __forceinline__ void cp_async16(uint32_t smem_addr, const void* gptr) {
    asm volatile("cp.async.cg.shared.global [%0], [%1], 16;"
                 :: "r"(smem_addr), "l"(gptr) : "memory");
}
__device__ __forceinline__ void cp_async_commit() {
    asm volatile("cp.async.commit_group;" ::: "memory");
}
template <int N>
__device__ __forceinline__ void cp_async_wait() {
    asm volatile("cp.async.wait_group %0;" :: "n"(N) : "memory");
}

// mma.sync m16n8k16 bf16 -> f32, row-major A, col-major B
__device__ __forceinline__ void mma16816(float* c,
                                         uint32_t a0, uint32_t a1, uint32_t a2, uint32_t a3,
                                         uint32_t b0, uint32_t b1) {
    asm volatile(
        "mma.sync.aligned.m16n8k16.row.col.f32.bf16.bf16.f32 "
        "{%0,%1,%2,%3}, {%4,%5,%6,%7}, {%8,%9}, {%0,%1,%2,%3};"
        : "+f"(c[0]), "+f"(c[1]), "+f"(c[2]), "+f"(c[3])
        : "r"(a0), "r"(a1), "r"(a2), "r"(a3), "r"(b0), "r"(b1));
}

// ============================================================================
// SMEM layout for GEMM kernel (dynamic):
//   A tile: 128 x LDA bf16  = 67584 B
//   B tile: 128 x LDA bf16  = 67584 B
//   srow  : 128 floats      = 512 B
// ============================================================================
static constexpr int SMEM_A_OFF = 0;
static constexpr int SMEM_B_OFF = MT * LDA * 2;                 // 67584
static constexpr int SMEM_R_OFF = SMEM_B_OFF + NT * LDA * 2;    // 135168
static constexpr int SMEM_TOTAL = SMEM_R_OFF + 128 * 4;         // 135680

// ============================================================================
// Kernel 1: L2-normalize rows of [z_augment; z_orig] -> bf16, row-major
// ============================================================================
__global__ void __launch_bounds__(256) normalize_kernel(
    const float* __restrict__ z_orig,
    const float* __restrict__ z_aug
) {
    int wid = threadIdx.x >> 5;
    int lid = threadIdx.x & 31;
    int row = blockIdx.x * 8 + wid;   // 1024 blocks * 8 warps = 8192 rows

    const float* src = (row < BATCH) ? (z_aug + (size_t)row * DIM)
                                     : (z_orig + (size_t)(row - BATCH) * DIM);
    float4 v0 = reinterpret_cast<const float4*>(src)[lid * 2];
    float4 v1 = reinterpret_cast<const float4*>(src)[lid * 2 + 1];

    float s = v0.x * v0.x + v0.y * v0.y + v0.z * v0.z + v0.w * v0.w
            + v1.x * v1.x + v1.y * v1.y + v1.z * v1.z + v1.w * v1.w;
    #pragma unroll
    for (int o = 16; o; o >>= 1) s += __shfl_xor_sync(0xffffffffu, s, o);

    float inv = 1.0f / fmaxf(sqrtf(s), 1e-8f);

    union { uint4 u; __nv_bfloat16 h[8]; } out;
    out.h[0] = __float2bfloat16(v0.x * inv);
    out.h[1] = __float2bfloat16(v0.y * inv);
    out.h[2] = __float2bfloat16(v0.z * inv);
    out.h[3] = __float2bfloat16(v0.w * inv);
    out.h[4] = __float2bfloat16(v1.x * inv);
    out.h[5] = __float2bfloat16(v1.y * inv);
    out.h[6] = __float2bfloat16(v1.z * inv);
    out.h[7] = __float2bfloat16(v1.w * inv);
    reinterpret_cast<uint4*>(g_zn + (size_t)row * DIM)[lid] = out.u;
}

// ============================================================================
// Kernel 2: 128x128 tile GEMM (mma.sync bf16) + exp epilogue + row-sum atomics
// ============================================================================
__global__ void __launch_bounds__(256, 1)
gemm_exp_kernel() {
    extern __shared__ char smem[];
    uint32_t smem_base = smem_to_u32(smem);
    float* srow = reinterpret_cast<float*>(smem + SMEM_R_OFF);

    int tid = threadIdx.x;
    int wid = tid >> 5;
    int lane = tid & 31;
    int gid = lane >> 2;       // "groupID"  (0..7)
    int tig = lane & 3;        // thread-in-group (0..3)

    int it = blockIdx.x >> 6;  // 0..63  (M tile)
    int jt = blockIdx.x & 63;  // 0..63  (N tile)

    int wm = wid >> 1;         // 0..3 : warp rows  wm*32 .. +32
    int wn = wid & 1;          // 0..1 : warp cols  wn*64 .. +64

    // --- async load, split K into two halves for load/MMA overlap ---
    // A tile rows: it*128 .. +128 ; B tile rows: jt*128 .. +128 (stored [n][k])
    const char* gz = reinterpret_cast<const char*>(g_zn);
    #pragma unroll
    for (int h = 0; h < 2; h++) {
        // 2048 16B-vectors for A + 2048 for B per half; 256 threads
        #pragma unroll
        for (int x = 0; x < 8; x++) {
            int v = x * 256 + tid;          // 0..2047
            int row = v >> 4;               // 0..127
            int v8  = v & 15;               // 16-byte vector within half
            int kb  = h * 256 + v8 * 16;    // byte offset in K (bf16*2)
            cp_async16(smem_base + SMEM_A_OFF + (uint32_t)(row * (LDA*2) + kb),
                       gz + ((size_t)(it * MT + row) * DIM) * 2 + kb);
        }
        #pragma unroll
        for (int x = 0; x < 8; x++) {
            int v = x * 256 + tid;
            int row = v >> 4;
            int v8  = v & 15;
            int kb  = h * 256 + v8 * 16;
            cp_async16(smem_base + SMEM_B_OFF + (uint32_t)(row * (LDA*2) + kb),
                       gz + ((size_t)(jt * NT + row) * DIM) * 2 + kb);
        }
        cp_async_commit();
    }

    if (tid < 128) srow[tid] = 0.0f;

    const uint32_t* As32 = reinterpret_cast<const uint32_t*>(smem + SMEM_A_OFF);
    const uint32_t* Bs32 = reinterpret_cast<const uint32_t*>(smem + SMEM_B_OFF);

    float acc[2][8][4];
    #pragma unroll
    for (int mf = 0; mf < 2; mf++)
        #pragma unroll
        for (int nf = 0; nf < 8; nf++)
            #pragma unroll
            for (int q = 0; q < 4; q++) acc[mf][nf][q] = 0.0f;

    // --- MMA mainloop: two K-halves, 8 k-steps of 16 each ---
    #pragma unroll
    for (int h = 0; h < 2; h++) {
        if (h == 0) cp_async_wait<1>(); else cp_async_wait<0>();
        __syncthreads();

        #pragma unroll
        for (int kk = 0; kk < 8; kk++) {
            int k0 = h * 128 + kk * 16;

            uint32_t a[2][4];
            #pragma unroll
            for (int mf = 0; mf < 2; mf++) {
                int rb = wm * 32 + mf * 16;
                int r0 = rb + gid;
                a[mf][0] = As32[(r0       * LDA + k0 + tig * 2)     >> 1];
                a[mf][1] = As32[((r0 + 8) * LDA + k0 + tig * 2)     >> 1];
                a[mf][2] = As32[(r0       * LDA + k0 + 8 + tig * 2) >> 1];
                a[mf][3] = As32[((r0 + 8) * LDA + k0 + 8 + tig * 2) >> 1];
            }
            uint32_t b[8][2];
            #pragma unroll
            for (int nf = 0; nf < 8; nf++) {
                int n = wn * 64 + nf * 8 + gid;
                b[nf][0] = Bs32[(n * LDA + k0 + tig * 2)     >> 1];
                b[nf][1] = Bs32[(n * LDA + k0 + 8 + tig * 2) >> 1];
            }
            #pragma unroll
            for (int mf = 0; mf < 2; mf++)
                #pragma unroll
                for (int nf = 0; nf < 8; nf++)
                    mma16816(acc[mf][nf], a[mf][0], a[mf][1], a[mf][2], a[mf][3],
                             b[nf][0], b[nf][1]);
        }
    }

    // --- Epilogue: exp, diagonal mask, per-row reduction ---
    // Thread covers rows {wm*32 + mf*16 + gid, +8} and cols {wn*64+nf*8+tig*2, +1}
    float rsum[4] = {0.f, 0.f, 0.f, 0.f};   // [mf*2 + half]
    int gj_base = jt * NT + wn * 64 + tig * 2;
    #pragma unroll
    for (int mf = 0; mf < 2; mf++) {
        int gi0 = it * MT + wm * 32 + mf * 16 + gid;   // rows for c0,c1
        int gi1 = gi0 + 8;                             // rows for c2,c3
        #pragma unroll
        for (int nf = 0; nf < 8; nf++) {
            int j0 = gj_base + nf * 8;
            float e0 = __expf(acc[mf][nf][0] * INV_TAU);
            float e1 = __expf(acc[mf][nf][1] * INV_TAU);
            float e2 = __expf(acc[mf][nf][2] * INV_TAU);
            float e3 = __expf(acc[mf][nf][3] * INV_TAU);
            if (j0     == gi0) e0 = 0.0f;
            if (j0 + 1 == gi0) e1 = 0.0f;
            if (j0     == gi1) e2 = 0.0f;
            if (j0 + 1 == gi1) e3 = 0.0f;
            rsum[mf * 2 + 0] += e0 + e1;
            rsum[mf * 2 + 1] += e2 + e3;
        }
    }
    // reduce across the 4 lanes of each group (they share the same rows)
    #pragma unroll
    for (int q = 0; q < 4; q++) {
        rsum[q] += __shfl_xor_sync(0xffffffffu, rsum[q], 1);
        rsum[q] += __shfl_xor_sync(0xffffffffu, rsum[q], 2);
    }
    if (tig == 0) {
        int rb = wm * 32 + gid;
        atomicAdd(&srow[rb],      rsum[0]);
        atomicAdd(&srow[rb + 8],  rsum[1]);
        atomicAdd(&srow[rb + 16], rsum[2]);
        atomicAdd(&srow[rb + 24], rsum[3]);
    }
    __syncthreads();
    if (tid < 128) atomicAdd(&g_rowsum[it * MT + tid], srow[tid]);
}

// ============================================================================
// Kernel 3: positives + log(rowsum) + final scalar reduction
//   loss = sum_i (-pos_i/tau + log(rowsum_i)) / NROWS
// ============================================================================
__global__ void __launch_bounds__(256) loss_kernel(float* __restrict__ out) {
    __shared__ float bsum;
    int wid = threadIdx.x >> 5;
    int lid = threadIdx.x & 31;
    if (threadIdx.x == 0) bsum = 0.0f;
    __syncthreads();

    int i = blockIdx.x * 8 + wid;               // 1024 blocks * 8 warps
    int p = (i < BATCH) ? i + BATCH : i - BATCH;

    union { uint4 u; __nv_bfloat16 h[8]; } a, b;
    a.u = reinterpret_cast<const uint4*>(g_zn + (size_t)i * DIM)[lid];
    b.u = reinterpret_cast<const uint4*>(g_zn + (size_t)p * DIM)[lid];
    float d = 0.0f;
    #pragma unroll
    for (int q = 0; q < 8; q++)
        d += __bfloat162float(a.h[q]) * __bfloat162float(b.h[q]);
    #pragma unroll
    for (int o = 16; o; o >>= 1) d += __shfl_xor_sync(0xffffffffu, d, o);

    if (lid == 0) {
        float v = (-INV_TAU * d + logf(g_rowsum[i])) * (1.0f / (float)NROWS);
        atomicAdd(&bsum, v);
    }
    __syncthreads();
    if (threadIdx.x == 0) atomicAdd(out, bsum);
}

// ============================================================================
// kernel_launch
// ============================================================================
extern "C" void kernel_launch(void* const* d_in, const int* in_sizes, int n_in,
                              void* d_out, int out_size) {
    (void)in_sizes; (void)n_in;
    const float* z_orig = (const float*)d_in[0];   // metadata order: z_orig first
    const float* z_aug  = (const float*)d_in[1];
    float* out = (float*)d_out;

    void* rs_addr = nullptr;
    cudaGetSymbolAddress(&rs_addr, g_rowsum);
    cudaMemsetAsync(rs_addr, 0, NROWS * sizeof(float), 0);
    cudaMemsetAsync(out, 0, (size_t)out_size * sizeof(float), 0);

    normalize_kernel<<<1024, 256>>>(z_orig, z_aug);

    cudaFuncSetAttribute(gemm_exp_kernel,
                         cudaFuncAttributeMaxDynamicSharedMemorySize, SMEM_TOTAL);
    gemm_exp_kernel<<<N_ITILE * N_JTILE, 256, SMEM_TOTAL>>>();

    loss_kernel<<<1024, 256>>>(out);
}

// round 4
// speedup vs baseline: 1.6417x; 1.6417x over previous
#include <cuda_runtime.h>
#include <cuda_bf16.h>
#include <cstdint>

// ============================================================================
// Problem constants
// ============================================================================
#define BATCH   4096
#define DIM     256
#define NROWS   8192          // 2*BATCH
#define INV_TAU 2.0f          // 1/0.5

// GEMM tiling: 128x128 output tile, K=256 fully resident, upper-tri tiles only
#define MT      128
#define NT      128
#define NTILE   64            // 64x64 tile grid; we do jt >= it: 2080 CTAs
#define N_CTAS  (NTILE * (NTILE + 1) / 2)
#define LDA     264           // padded row length in bf16 (+16B) -> conflict-free
#define LDAB    (LDA * 2)     // row stride in bytes (528)

// ============================================================================
// Device-global scratch (no dynamic allocation allowed)
// ============================================================================
__device__ __align__(16) __nv_bfloat16 g_zn[NROWS * DIM];  // normalized, bf16
__device__ float g_rowsum[NROWS];

// ============================================================================
// Helpers
// ============================================================================
__device__ __forceinline__ uint32_t smem_to_u32(const void* smem_ptr) {
    uint32_t addr;
    asm("{ .reg .u64 tmp; cvta.to.shared.u64 tmp, %1; cvt.u32.u64 %0, tmp; }"
        : "=r"(addr) : "l"(smem_ptr));
    return addr;
}

__device__ __forceinline__ void cp_async16(uint32_t smem_addr, const void* gptr) {
    asm volatile("cp.async.cg.shared.global [%0], [%1], 16;"
                 :: "r"(smem_addr), "l"(gptr) : "memory");
}
__device__ __forceinline__ void cp_async_commit() {
    asm volatile("cp.async.commit_group;" ::: "memory");
}
template <int N>
__device__ __forceinline__ void cp_async_wait() {
    asm volatile("cp.async.wait_group %0;" :: "n"(N) : "memory");
}

__device__ __forceinline__ void ldmatrix_x4(uint32_t& r0, uint32_t& r1,
                                            uint32_t& r2, uint32_t& r3,
                                            uint32_t addr) {
    asm volatile("ldmatrix.sync.aligned.m8n8.x4.shared.b16 {%0,%1,%2,%3}, [%4];"
                 : "=r"(r0), "=r"(r1), "=r"(r2), "=r"(r3) : "r"(addr));
}

// mma.sync m16n8k16 bf16 -> f32, row-major A, col-major B
__device__ __forceinline__ void mma16816(float* c,
                                         uint32_t a0, uint32_t a1, uint32_t a2, uint32_t a3,
                                         uint32_t b0, uint32_t b1) {
    asm volatile(
        "mma.sync.aligned.m16n8k16.row.col.f32.bf16.bf16.f32 "
        "{%0,%1,%2,%3}, {%4,%5,%6,%7}, {%8,%9}, {%0,%1,%2,%3};"
        : "+f"(c[0]), "+f"(c[1]), "+f"(c[2]), "+f"(c[3])
        : "r"(a0), "r"(a1), "r"(a2), "r"(a3), "r"(b0), "r"(b1));
}

// ============================================================================
// SMEM layout for GEMM kernel (dynamic):
//   A tile: 128 x LDA bf16  = 67584 B
//   B tile: 128 x LDA bf16  = 67584 B
//   srow  : 128 floats, scol: 128 floats
// ============================================================================
static constexpr int SMEM_A_OFF = 0;
static constexpr int SMEM_B_OFF = MT * LDAB;                    // 67584
static constexpr int SMEM_R_OFF = SMEM_B_OFF + NT * LDAB;       // 135168
static constexpr int SMEM_C_OFF = SMEM_R_OFF + 128 * 4;         // 135680
static constexpr int SMEM_TOTAL = SMEM_C_OFF + 128 * 4;         // 136192

// ============================================================================
// Kernel 1: L2-normalize rows of [z_augment; z_orig] -> bf16, row-major
// ============================================================================
__global__ void __launch_bounds__(256) normalize_kernel(
    const float* __restrict__ z_orig,
    const float* __restrict__ z_aug
) {
    int wid = threadIdx.x >> 5;
    int lid = threadIdx.x & 31;
    int row = blockIdx.x * 8 + wid;   // 1024 blocks * 8 warps = 8192 rows

    const float* src = (row < BATCH) ? (z_aug + (size_t)row * DIM)
                                     : (z_orig + (size_t)(row - BATCH) * DIM);
    float4 v0 = reinterpret_cast<const float4*>(src)[lid * 2];
    float4 v1 = reinterpret_cast<const float4*>(src)[lid * 2 + 1];

    float s = v0.x * v0.x + v0.y * v0.y + v0.z * v0.z + v0.w * v0.w
            + v1.x * v1.x + v1.y * v1.y + v1.z * v1.z + v1.w * v1.w;
    #pragma unroll
    for (int o = 16; o; o >>= 1) s += __shfl_xor_sync(0xffffffffu, s, o);

    float inv = 1.0f / fmaxf(sqrtf(s), 1e-8f);

    union { uint4 u; __nv_bfloat16 h[8]; } out;
    out.h[0] = __float2bfloat16(v0.x * inv);
    out.h[1] = __float2bfloat16(v0.y * inv);
    out.h[2] = __float2bfloat16(v0.z * inv);
    out.h[3] = __float2bfloat16(v0.w * inv);
    out.h[4] = __float2bfloat16(v1.x * inv);
    out.h[5] = __float2bfloat16(v1.y * inv);
    out.h[6] = __float2bfloat16(v1.z * inv);
    out.h[7] = __float2bfloat16(v1.w * inv);
    reinterpret_cast<uint4*>(g_zn + (size_t)row * DIM)[lid] = out.u;
}

// ============================================================================
// Kernel 2: upper-triangular 128x128 tile GEMM (mma.sync bf16, ldmatrix)
//           + exp epilogue + row-sum AND col-sum atomics (symmetry)
// ============================================================================
__global__ void __launch_bounds__(256, 1)
gemm_exp_kernel() {
    extern __shared__ char smem[];
    uint32_t smem_base = smem_to_u32(smem);
    float* srow = reinterpret_cast<float*>(smem + SMEM_R_OFF);
    float* scol = reinterpret_cast<float*>(smem + SMEM_C_OFF);

    int tid = threadIdx.x;
    int wid = tid >> 5;
    int lane = tid & 31;
    int gid = lane >> 2;       // "groupID"  (0..7)
    int tig = lane & 3;        // thread-in-group (0..3)
    int sub = lane >> 3;       // ldmatrix address group (0..3)
    int li  = lane & 7;        // lane within group

    // --- decode (it, jt) with jt >= it from linear CTA id ---
    int t = blockIdx.x;
    int it = 0;
    {
        int rem = NTILE;
        while (t >= rem) { t -= rem; rem--; it++; }
    }
    int jt = it + t;
    bool diag = (it == jt);

    int wm = wid >> 1;         // 0..3 : warp rows  wm*32 .. +32
    int wn = wid & 1;          // 0..1 : warp cols  wn*64 .. +64

    // --- async load, split K into two halves ---
    const char* gz = reinterpret_cast<const char*>(g_zn);
    #pragma unroll
    for (int h = 0; h < 2; h++) {
        #pragma unroll
        for (int x = 0; x < 8; x++) {
            int v = x * 256 + tid;          // 0..2047
            int row = v >> 4;               // 0..127
            int v8  = v & 15;               // 16-byte vector within half
            int kb  = h * 256 + v8 * 16;    // byte offset in K
            cp_async16(smem_base + SMEM_A_OFF + (uint32_t)(row * LDAB + kb),
                       gz + ((size_t)(it * MT + row) * DIM) * 2 + kb);
        }
        #pragma unroll
        for (int x = 0; x < 8; x++) {
            int v = x * 256 + tid;
            int row = v >> 4;
            int v8  = v & 15;
            int kb  = h * 256 + v8 * 16;
            cp_async16(smem_base + SMEM_B_OFF + (uint32_t)(row * LDAB + kb),
                       gz + ((size_t)(jt * NT + row) * DIM) * 2 + kb);
        }
        cp_async_commit();
    }

    if (tid < 128) { srow[tid] = 0.0f; scol[tid] = 0.0f; }

    // ldmatrix per-lane base addresses
    // A x4 (16x16 fragment): groups g0..g3 = (rows+0,k0) (rows+8,k0) (rows+0,k0+8) (rows+8,k0+8)
    uint32_t baseA = smem_base + SMEM_A_OFF
                   + (uint32_t)((wm * 32 + (sub & 1) * 8 + li) * LDAB + (sub >> 1) * 16);
    // B x4 (two 8-col blocks): g0..g3 = (n+0,k0) (n+0,k0+8) (n+8,k0) (n+8,k0+8)
    uint32_t baseB = smem_base + SMEM_B_OFF
                   + (uint32_t)((wn * 64 + (sub >> 1) * 8 + li) * LDAB + (sub & 1) * 16);

    float acc[2][8][4];
    #pragma unroll
    for (int mf = 0; mf < 2; mf++)
        #pragma unroll
        for (int nf = 0; nf < 8; nf++)
            #pragma unroll
            for (int q = 0; q < 4; q++) acc[mf][nf][q] = 0.0f;

    // --- MMA mainloop: two K-halves, 8 k-steps of 16 each ---
    #pragma unroll
    for (int h = 0; h < 2; h++) {
        if (h == 0) cp_async_wait<1>(); else cp_async_wait<0>();
        __syncthreads();

        #pragma unroll
        for (int kk = 0; kk < 8; kk++) {
            uint32_t kb = (uint32_t)((h * 128 + kk * 16) * 2);

            uint32_t a[2][4];
            #pragma unroll
            for (int mf = 0; mf < 2; mf++)
                ldmatrix_x4(a[mf][0], a[mf][1], a[mf][2], a[mf][3],
                            baseA + (uint32_t)(mf * 16 * LDAB) + kb);

            uint32_t b[8][2];
            #pragma unroll
            for (int nfp = 0; nfp < 8; nfp += 2)
                ldmatrix_x4(b[nfp][0], b[nfp][1], b[nfp + 1][0], b[nfp + 1][1],
                            baseB + (uint32_t)(nfp * 8 * LDAB) + kb);

            #pragma unroll
            for (int mf = 0; mf < 2; mf++)
                #pragma unroll
                for (int nf = 0; nf < 8; nf++)
                    mma16816(acc[mf][nf], a[mf][0], a[mf][1], a[mf][2], a[mf][3],
                             b[nf][0], b[nf][1]);
        }
    }

    // --- Epilogue: exp in place (mask diagonal only on diag tiles) ---
    // Thread covers rows {wm*32+mf*16+gid, +8}, cols {wn*64+nf*8+tig*2, +1}
    if (diag) {
        int r0l = wm * 32 + gid;            // local row for c0,c1 (mf=0)
        int c0l = wn * 64 + tig * 2;
        #pragma unroll
        for (int mf = 0; mf < 2; mf++) {
            int lr0 = r0l + mf * 16, lr1 = lr0 + 8;
            #pragma unroll
            for (int nf = 0; nf < 8; nf++) {
                int lc = c0l + nf * 8;
                float e0 = __expf(acc[mf][nf][0] * INV_TAU);
                float e1 = __expf(acc[mf][nf][1] * INV_TAU);
                float e2 = __expf(acc[mf][nf][2] * INV_TAU);
                float e3 = __expf(acc[mf][nf][3] * INV_TAU);
                if (lc     == lr0) e0 = 0.0f;
                if (lc + 1 == lr0) e1 = 0.0f;
                if (lc     == lr1) e2 = 0.0f;
                if (lc + 1 == lr1) e3 = 0.0f;
                acc[mf][nf][0] = e0; acc[mf][nf][1] = e1;
                acc[mf][nf][2] = e2; acc[mf][nf][3] = e3;
            }
        }
    } else {
        #pragma unroll
        for (int mf = 0; mf < 2; mf++)
            #pragma unroll
            for (int nf = 0; nf < 8; nf++)
                #pragma unroll
                for (int q = 0; q < 4; q++)
                    acc[mf][nf][q] = __expf(acc[mf][nf][q] * INV_TAU);
    }

    // --- row sums: reduce over columns (nf, col-pairs, then tig lanes) ---
    {
        float rsum[4] = {0.f, 0.f, 0.f, 0.f};   // [mf*2 + rowhalf]
        #pragma unroll
        for (int mf = 0; mf < 2; mf++)
            #pragma unroll
            for (int nf = 0; nf < 8; nf++) {
                rsum[mf * 2 + 0] += acc[mf][nf][0] + acc[mf][nf][1];
                rsum[mf * 2 + 1] += acc[mf][nf][2] + acc[mf][nf][3];
            }
        #pragma unroll
        for (int q = 0; q < 4; q++) {
            rsum[q] += __shfl_xor_sync(0xffffffffu, rsum[q], 1);
            rsum[q] += __shfl_xor_sync(0xffffffffu, rsum[q], 2);
        }
        if (tig == 0) {
            int rb = wm * 32 + gid;
            atomicAdd(&srow[rb],      rsum[0]);
            atomicAdd(&srow[rb + 8],  rsum[1]);
            atomicAdd(&srow[rb + 16], rsum[2]);
            atomicAdd(&srow[rb + 24], rsum[3]);
        }
    }

    // --- col sums (only needed off-diagonal): reduce over rows ---
    if (!diag) {
        float csum[8][2];
        #pragma unroll
        for (int nf = 0; nf < 8; nf++) {
            csum[nf][0] = acc[0][nf][0] + acc[0][nf][2] + acc[1][nf][0] + acc[1][nf][2];
            csum[nf][1] = acc[0][nf][1] + acc[0][nf][3] + acc[1][nf][1] + acc[1][nf][3];
        }
        // reduce across gid (lanes with same tig, stride 4,8,16 share columns)
        #pragma unroll
        for (int nf = 0; nf < 8; nf++)
            #pragma unroll
            for (int q = 0; q < 2; q++) {
                csum[nf][q] += __shfl_xor_sync(0xffffffffu, csum[nf][q], 4);
                csum[nf][q] += __shfl_xor_sync(0xffffffffu, csum[nf][q], 8);
                csum[nf][q] += __shfl_xor_sync(0xffffffffu, csum[nf][q], 16);
            }
        if (gid == 0) {
            #pragma unroll
            for (int nf = 0; nf < 8; nf++) {
                int cb = wn * 64 + nf * 8 + tig * 2;
                atomicAdd(&scol[cb],     csum[nf][0]);
                atomicAdd(&scol[cb + 1], csum[nf][1]);
            }
        }
    }

    __syncthreads();
    if (tid < 128) {
        atomicAdd(&g_rowsum[it * MT + tid], srow[tid]);
        if (!diag) atomicAdd(&g_rowsum[jt * NT + tid], scol[tid]);
    }
}

// ============================================================================
// Kernel 3: positives + log(rowsum) + final scalar reduction
//   loss = sum_i (-pos_i/tau + log(rowsum_i)) / NROWS
// ============================================================================
__global__ void __launch_bounds__(256) loss_kernel(float* __restrict__ out) {
    __shared__ float bsum;
    int wid = threadIdx.x >> 5;
    int lid = threadIdx.x & 31;
    if (threadIdx.x == 0) bsum = 0.0f;
    __syncthreads();

    int i = blockIdx.x * 8 + wid;               // 1024 blocks * 8 warps
    int p = (i < BATCH) ? i + BATCH : i - BATCH;

    union { uint4 u; __nv_bfloat16 h[8]; } a, b;
    a.u = reinterpret_cast<const uint4*>(g_zn + (size_t)i * DIM)[lid];
    b.u = reinterpret_cast<const uint4*>(g_zn + (size_t)p * DIM)[lid];
    float d = 0.0f;
    #pragma unroll
    for (int q = 0; q < 8; q++)
        d += __bfloat162float(a.h[q]) * __bfloat162float(b.h[q]);
    #pragma unroll
    for (int o = 16; o; o >>= 1) d += __shfl_xor_sync(0xffffffffu, d, o);

    if (lid == 0) {
        float v = (-INV_TAU * d + logf(g_rowsum[i])) * (1.0f / (float)NROWS);
        atomicAdd(&bsum, v);
    }
    __syncthreads();
    if (threadIdx.x == 0) atomicAdd(out, bsum);
}

// ============================================================================
// kernel_launch
// ============================================================================
extern "C" void kernel_launch(void* const* d_in, const int* in_sizes, int n_in,
                              void* d_out, int out_size) {
    (void)in_sizes; (void)n_in;
    const float* z_orig = (const float*)d_in[0];
    const float* z_aug  = (const float*)d_in[1];
    float* out = (float*)d_out;

    void* rs_addr = nullptr;
    cudaGetSymbolAddress(&rs_addr, g_rowsum);
    cudaMemsetAsync(rs_addr, 0, NROWS * sizeof(float), 0);
    cudaMemsetAsync(out, 0, (size_t)out_size * sizeof(float), 0);

    normalize_kernel<<<1024, 256>>>(z_orig, z_aug);

    cudaFuncSetAttribute(gemm_exp_kernel,
                         cudaFuncAttributeMaxDynamicSharedMemorySize, SMEM_TOTAL);
    gemm_exp_kernel<<<N_CTAS, 256, SMEM_TOTAL>>>();

    loss_kernel<<<1024, 256>>>(out);
}

// round 5
// speedup vs baseline: 2.4879x; 1.5154x over previous
#include <cuda_runtime.h>
#include <cuda_bf16.h>
#include <cstdint>

// ============================================================================
// Problem constants
// ============================================================================
#define BATCH   4096
#define DIM     256
#define NROWS   8192          // 2*BATCH
#define INV_TAU 2.0f          // 1/0.5

// GEMM tiling: 128x128 output tile, K chunked by 64, upper-tri tiles only
#define MT      128
#define NT      128
#define NTILE   64            // 64x64 tile grid; jt >= it: 2080 CTAs
#define N_CTAS  (NTILE * (NTILE + 1) / 2)
#define KC      64            // K elements per chunk (128 bytes)
#define NCHUNK  4             // DIM / KC
#define NSTAGE  3

// ============================================================================
// Device-global scratch
// ============================================================================
__device__ __align__(16) __nv_bfloat16 g_zn[NROWS * DIM];  // normalized, bf16
__device__ float g_rowsum[NROWS];

// ============================================================================
// Helpers
// ============================================================================
__device__ __forceinline__ uint32_t smem_to_u32(const void* smem_ptr) {
    uint32_t addr;
    asm("{ .reg .u64 tmp; cvta.to.shared.u64 tmp, %1; cvt.u32.u64 %0, tmp; }"
        : "=r"(addr) : "l"(smem_ptr));
    return addr;
}

__device__ __forceinline__ void cp_async16(uint32_t smem_addr, const void* gptr) {
    asm volatile("cp.async.cg.shared.global [%0], [%1], 16;"
                 :: "r"(smem_addr), "l"(gptr) : "memory");
}
__device__ __forceinline__ void cp_async_commit() {
    asm volatile("cp.async.commit_group;" ::: "memory");
}
template <int N>
__device__ __forceinline__ void cp_async_wait() {
    asm volatile("cp.async.wait_group %0;" :: "n"(N) : "memory");
}

__device__ __forceinline__ void ldmatrix_x4(uint32_t& r0, uint32_t& r1,
                                            uint32_t& r2, uint32_t& r3,
                                            uint32_t addr) {
    asm volatile("ldmatrix.sync.aligned.m8n8.x4.shared.b16 {%0,%1,%2,%3}, [%4];"
                 : "=r"(r0), "=r"(r1), "=r"(r2), "=r"(r3) : "r"(addr));
}

// mma.sync m16n8k16 bf16 -> f32, row-major A, col-major B
__device__ __forceinline__ void mma16816(float* c,
                                         uint32_t a0, uint32_t a1, uint32_t a2, uint32_t a3,
                                         uint32_t b0, uint32_t b1) {
    asm volatile(
        "mma.sync.aligned.m16n8k16.row.col.f32.bf16.bf16.f32 "
        "{%0,%1,%2,%3}, {%4,%5,%6,%7}, {%8,%9}, {%0,%1,%2,%3};"
        : "+f"(c[0]), "+f"(c[1]), "+f"(c[2]), "+f"(c[3])
        : "r"(a0), "r"(a1), "r"(a2), "r"(a3), "r"(b0), "r"(b1));
}

// SW128-style swizzle for 128-byte rows: flip 16B-chunk index by (row mod 8)
#define SWZ(off) ((off) ^ (((off) >> 3) & 0x70))

// ============================================================================
// SMEM layout (dynamic): NSTAGE stages of {A:128x128B, B:128x128B}
// ============================================================================
static constexpr int STAGE_A    = 0;
static constexpr int STAGE_B    = 16384;
static constexpr int STAGE_SZ   = 32768;
static constexpr int SMEM_R_OFF = NSTAGE * STAGE_SZ;            // 98304
static constexpr int SMEM_C_OFF = SMEM_R_OFF + 128 * 4;
static constexpr int SMEM_TOTAL = SMEM_C_OFF + 128 * 4;         // 99328

// ============================================================================
// Kernel 1: L2-normalize rows of [z_augment; z_orig] -> bf16, row-major
// ============================================================================
__global__ void __launch_bounds__(256) normalize_kernel(
    const float* __restrict__ z_orig,
    const float* __restrict__ z_aug
) {
    int wid = threadIdx.x >> 5;
    int lid = threadIdx.x & 31;
    int row = blockIdx.x * 8 + wid;

    const float* src = (row < BATCH) ? (z_aug + (size_t)row * DIM)
                                     : (z_orig + (size_t)(row - BATCH) * DIM);
    float4 v0 = reinterpret_cast<const float4*>(src)[lid * 2];
    float4 v1 = reinterpret_cast<const float4*>(src)[lid * 2 + 1];

    float s = v0.x * v0.x + v0.y * v0.y + v0.z * v0.z + v0.w * v0.w
            + v1.x * v1.x + v1.y * v1.y + v1.z * v1.z + v1.w * v1.w;
    #pragma unroll
    for (int o = 16; o; o >>= 1) s += __shfl_xor_sync(0xffffffffu, s, o);

    float inv = 1.0f / fmaxf(sqrtf(s), 1e-8f);

    union { uint4 u; __nv_bfloat16 h[8]; } out;
    out.h[0] = __float2bfloat16(v0.x * inv);
    out.h[1] = __float2bfloat16(v0.y * inv);
    out.h[2] = __float2bfloat16(v0.z * inv);
    out.h[3] = __float2bfloat16(v0.w * inv);
    out.h[4] = __float2bfloat16(v1.x * inv);
    out.h[5] = __float2bfloat16(v1.y * inv);
    out.h[6] = __float2bfloat16(v1.z * inv);
    out.h[7] = __float2bfloat16(v1.w * inv);
    reinterpret_cast<uint4*>(g_zn + (size_t)row * DIM)[lid] = out.u;
}

// ============================================================================
// Kernel 2: upper-tri 128x128 tile GEMM, K-chunked 3-stage cp.async pipeline,
//           swizzled smem, exp epilogue, row+col sum atomics (symmetry)
// ============================================================================
__global__ void __launch_bounds__(256, 2)
gemm_exp_kernel() {
    extern __shared__ char smem[];
    uint32_t smem_base = smem_to_u32(smem);
    float* srow = reinterpret_cast<float*>(smem + SMEM_R_OFF);
    float* scol = reinterpret_cast<float*>(smem + SMEM_C_OFF);

    int tid  = threadIdx.x;
    int wid  = tid >> 5;
    int lane = tid & 31;
    int gid  = lane >> 2;      // 0..7
    int tig  = lane & 3;       // 0..3
    int sub  = lane >> 3;      // 0..3
    int li   = lane & 7;       // 0..7

    // --- decode (it, jt) with jt >= it ---
    int t = blockIdx.x;
    int it = 0;
    {
        int rem = NTILE;
        while (t >= rem) { t -= rem; rem--; it++; }
    }
    int jt = it + t;
    bool diag = (it == jt);

    int wm = wid >> 1;         // 0..3
    int wn = wid & 1;          // 0..1

    const char* gz = reinterpret_cast<const char*>(g_zn);
    const char* gA = gz + (size_t)(it * MT) * DIM * 2;
    const char* gB = gz + (size_t)(jt * NT) * DIM * 2;

    // chunk loader: chunk c (K offset c*128 bytes) into stage s
    auto load_chunk = [&](int c, int s) {
        uint32_t sa = smem_base + (uint32_t)(s * STAGE_SZ);
        #pragma unroll
        for (int x = 0; x < 4; x++) {
            int v   = x * 256 + tid;        // 0..1023
            int row = v >> 3;
            int cv  = v & 7;
            uint32_t off = (uint32_t)(row * 128 + cv * 16);
            off = SWZ(off);
            const char* gofs = (const char*)0 + (size_t)row * (DIM * 2) + c * 128 + cv * 16;
            cp_async16(sa + STAGE_A + off, gA + (size_t)gofs);
            cp_async16(sa + STAGE_B + off, gB + (size_t)gofs);
        }
        cp_async_commit();
    };

    // --- prologue: fill stages 0..2 ---
    load_chunk(0, 0);
    load_chunk(1, 1);
    load_chunk(2, 2);
    if (tid < 128) { srow[tid] = 0.0f; scol[tid] = 0.0f; }

    // --- fragment address precompute (swizzled, per-lane constant XOR) ---
    int rowA = wm * 32 + (sub & 1) * 8 + li;
    int rowB = wn * 64 + (sub >> 1) * 8 + li;
    uint32_t xorA = (uint32_t)((rowA & 7) << 4);
    uint32_t xorB = (uint32_t)((rowB & 7) << 4);
    uint32_t baseA = (uint32_t)(rowA * 128) + STAGE_A;
    uint32_t baseB = (uint32_t)(rowB * 128) + STAGE_B;
    uint32_t colA[4], colB[4];
    #pragma unroll
    for (int kk = 0; kk < 4; kk++) {
        colA[kk] = ((uint32_t)((sub >> 1) * 16 + kk * 32)) ^ xorA;
        colB[kk] = ((uint32_t)((sub & 1) * 16 + kk * 32)) ^ xorB;
    }

    float acc[2][8][4];
    #pragma unroll
    for (int mf = 0; mf < 2; mf++)
        #pragma unroll
        for (int nf = 0; nf < 8; nf++)
            #pragma unroll
            for (int q = 0; q < 4; q++) acc[mf][nf][q] = 0.0f;

    // MMA over one resident chunk (4 k-steps of 16)
    auto mma_chunk = [&](int s) {
        uint32_t sa = smem_base + (uint32_t)(s * STAGE_SZ);
        #pragma unroll
        for (int kk = 0; kk < 4; kk++) {
            uint32_t a[2][4];
            #pragma unroll
            for (int mf = 0; mf < 2; mf++)
                ldmatrix_x4(a[mf][0], a[mf][1], a[mf][2], a[mf][3],
                            sa + baseA + (uint32_t)(mf * 16 * 128) + colA[kk]);
            uint32_t b[8][2];
            #pragma unroll
            for (int nfp = 0; nfp < 8; nfp += 2)
                ldmatrix_x4(b[nfp][0], b[nfp][1], b[nfp + 1][0], b[nfp + 1][1],
                            sa + baseB + (uint32_t)(nfp * 8 * 128) + colB[kk]);
            #pragma unroll
            for (int mf = 0; mf < 2; mf++)
                #pragma unroll
                for (int nf = 0; nf < 8; nf++)
                    mma16816(acc[mf][nf], a[mf][0], a[mf][1], a[mf][2], a[mf][3],
                             b[nf][0], b[nf][1]);
        }
    };

    // --- pipelined mainloop (4 chunks, 3 stages) ---
    cp_async_wait<2>(); __syncthreads();
    mma_chunk(0);
    __syncthreads();                 // everyone done reading stage 0
    load_chunk(3, 0);

    cp_async_wait<2>(); __syncthreads();
    mma_chunk(1);

    cp_async_wait<1>(); __syncthreads();
    mma_chunk(2);

    cp_async_wait<0>(); __syncthreads();
    mma_chunk(0);

    // --- Epilogue: exp in place (mask diagonal only on diag tiles) ---
    if (diag) {
        int r0l = wm * 32 + gid;
        int c0l = wn * 64 + tig * 2;
        #pragma unroll
        for (int mf = 0; mf < 2; mf++) {
            int lr0 = r0l + mf * 16, lr1 = lr0 + 8;
            #pragma unroll
            for (int nf = 0; nf < 8; nf++) {
                int lc = c0l + nf * 8;
                float e0 = __expf(acc[mf][nf][0] * INV_TAU);
                float e1 = __expf(acc[mf][nf][1] * INV_TAU);
                float e2 = __expf(acc[mf][nf][2] * INV_TAU);
                float e3 = __expf(acc[mf][nf][3] * INV_TAU);
                if (lc     == lr0) e0 = 0.0f;
                if (lc + 1 == lr0) e1 = 0.0f;
                if (lc     == lr1) e2 = 0.0f;
                if (lc + 1 == lr1) e3 = 0.0f;
                acc[mf][nf][0] = e0; acc[mf][nf][1] = e1;
                acc[mf][nf][2] = e2; acc[mf][nf][3] = e3;
            }
        }
    } else {
        #pragma unroll
        for (int mf = 0; mf < 2; mf++)
            #pragma unroll
            for (int nf = 0; nf < 8; nf++)
                #pragma unroll
                for (int q = 0; q < 4; q++)
                    acc[mf][nf][q] = __expf(acc[mf][nf][q] * INV_TAU);
    }

    // --- row sums ---
    {
        float rsum[4] = {0.f, 0.f, 0.f, 0.f};
        #pragma unroll
        for (int mf = 0; mf < 2; mf++)
            #pragma unroll
            for (int nf = 0; nf < 8; nf++) {
                rsum[mf * 2 + 0] += acc[mf][nf][0] + acc[mf][nf][1];
                rsum[mf * 2 + 1] += acc[mf][nf][2] + acc[mf][nf][3];
            }
        #pragma unroll
        for (int q = 0; q < 4; q++) {
            rsum[q] += __shfl_xor_sync(0xffffffffu, rsum[q], 1);
            rsum[q] += __shfl_xor_sync(0xffffffffu, rsum[q], 2);
        }
        if (tig == 0) {
            int rb = wm * 32 + gid;
            atomicAdd(&srow[rb],      rsum[0]);
            atomicAdd(&srow[rb + 8],  rsum[1]);
            atomicAdd(&srow[rb + 16], rsum[2]);
            atomicAdd(&srow[rb + 24], rsum[3]);
        }
    }

    // --- col sums (off-diagonal tiles only) ---
    if (!diag) {
        float csum[8][2];
        #pragma unroll
        for (int nf = 0; nf < 8; nf++) {
            csum[nf][0] = acc[0][nf][0] + acc[0][nf][2] + acc[1][nf][0] + acc[1][nf][2];
            csum[nf][1] = acc[0][nf][1] + acc[0][nf][3] + acc[1][nf][1] + acc[1][nf][3];
        }
        #pragma unroll
        for (int nf = 0; nf < 8; nf++)
            #pragma unroll
            for (int q = 0; q < 2; q++) {
                csum[nf][q] += __shfl_xor_sync(0xffffffffu, csum[nf][q], 4);
                csum[nf][q] += __shfl_xor_sync(0xffffffffu, csum[nf][q], 8);
                csum[nf][q] += __shfl_xor_sync(0xffffffffu, csum[nf][q], 16);
            }
        if (gid == 0) {
            #pragma unroll
            for (int nf = 0; nf < 8; nf++) {
                int cb = wn * 64 + nf * 8 + tig * 2;
                atomicAdd(&scol[cb],     csum[nf][0]);
                atomicAdd(&scol[cb + 1], csum[nf][1]);
            }
        }
    }

    __syncthreads();
    if (tid < 128) {
        atomicAdd(&g_rowsum[it * MT + tid], srow[tid]);
        if (!diag) atomicAdd(&g_rowsum[jt * NT + tid], scol[tid]);
    }
}

// ============================================================================
// Kernel 3: positives + log(rowsum) + final scalar reduction
// ============================================================================
__global__ void __launch_bounds__(256) loss_kernel(float* __restrict__ out) {
    __shared__ float bsum;
    int wid = threadIdx.x >> 5;
    int lid = threadIdx.x & 31;
    if (threadIdx.x == 0) bsum = 0.0f;
    __syncthreads();

    int i = blockIdx.x * 8 + wid;
    int p = (i < BATCH) ? i + BATCH : i - BATCH;

    union { uint4 u; __nv_bfloat16 h[8]; } a, b;
    a.u = reinterpret_cast<const uint4*>(g_zn + (size_t)i * DIM)[lid];
    b.u = reinterpret_cast<const uint4*>(g_zn + (size_t)p * DIM)[lid];
    float d = 0.0f;
    #pragma unroll
    for (int q = 0; q < 8; q++)
        d += __bfloat162float(a.h[q]) * __bfloat162float(b.h[q]);
    #pragma unroll
    for (int o = 16; o; o >>= 1) d += __shfl_xor_sync(0xffffffffu, d, o);

    if (lid == 0) {
        float v = (-INV_TAU * d + logf(g_rowsum[i])) * (1.0f / (float)NROWS);
        atomicAdd(&bsum, v);
    }
    __syncthreads();
    if (threadIdx.x == 0) atomicAdd(out, bsum);
}

// ============================================================================
// kernel_launch
// ============================================================================
extern "C" void kernel_launch(void* const* d_in, const int* in_sizes, int n_in,
                              void* d_out, int out_size) {
    (void)in_sizes; (void)n_in;
    const float* z_orig = (const float*)d_in[0];
    const float* z_aug  = (const float*)d_in[1];
    float* out = (float*)d_out;

    void* rs_addr = nullptr;
    cudaGetSymbolAddress(&rs_addr, g_rowsum);
    cudaMemsetAsync(rs_addr, 0, NROWS * sizeof(float), 0);
    cudaMemsetAsync(out, 0, (size_t)out_size * sizeof(float), 0);

    normalize_kernel<<<1024, 256>>>(z_orig, z_aug);

    cudaFuncSetAttribute(gemm_exp_kernel,
                         cudaFuncAttributeMaxDynamicSharedMemorySize, SMEM_TOTAL);
    gemm_exp_kernel<<<N_CTAS, 256, SMEM_TOTAL>>>();

    loss_kernel<<<1024, 256>>>(out);
}